// round 16
// baseline (speedup 1.0000x reference)
#include <cuda_runtime.h>
#include <cuda_fp16.h>

#define HID     1024
#define TSTEPS  4096
#define NCTA    128
#define NTH     512   // 16 warps: warp w -> rows 2w, 2w+1; pair (2j,2j+1) owns hidden j

// SMEM: h stage 4*2KB + sP 256B (weights live in registers)
#define SMEM_BYTES (4*2048 + 256)

// tagged h words: (tag << 32) | fp32 bits
__device__ __align__(16) unsigned long long g_h1q[2][HID];
__device__ __align__(16) unsigned long long g_h2q[2][HID];
__device__ unsigned g_cnt = 0;
__device__ unsigned g_gen = 0;

__device__ __forceinline__ float warpsum(float v) {
#pragma unroll
    for (int s = 16; s; s >>= 1) v += __shfl_xor_sync(0xffffffffu, v, s);
    return v;
}

__device__ __forceinline__ void gridbar() {   // used ONCE, after init
    __syncthreads();
    if (threadIdx.x == 0) {
        __threadfence();
        unsigned g = *((volatile unsigned*)&g_gen);
        if (atomicAdd(&g_cnt, 1u) == NCTA - 1) {
            atomicExch(&g_cnt, 0u);
            __threadfence();
            atomicExch(&g_gen, g + 1u);
        } else {
            while (*((volatile unsigned*)&g_gen) == g) { }
        }
    }
    __syncthreads();
}

__device__ __forceinline__ float sigf(float x) {
    return __fdividef(1.0f, 1.0f + __expf(-x));
}
__device__ __forceinline__ float tanhfast(float x) {
    return 2.0f * __fdividef(1.0f, 1.0f + __expf(-2.0f * x)) - 1.0f;
}

__device__ __forceinline__ void ldcg2q(const unsigned long long* p,
                                       unsigned long long& a, unsigned long long& b) {
    asm volatile("ld.global.cg.v2.u64 {%0,%1}, [%2];"
                 : "=l"(a), "=l"(b) : "l"(p));
}

// fused poll: own 2+2 words of h1/h2 until tags match, then stage to A/B slots
__device__ __forceinline__ void poll_stage(const unsigned long long* p1w,
                                           const unsigned long long* p2w,
                                           unsigned tg, float2* d1, float2* d2) {
    unsigned long long a0, a1, b0, b1;
    bool oka = false, okb = false;
    do {
        if (!oka) { ldcg2q(p1w, a0, a1);
                    oka = ((unsigned)(a0 >> 32) == tg) & ((unsigned)(a1 >> 32) == tg); }
        if (!okb) { ldcg2q(p2w, b0, b1);
                    okb = ((unsigned)(b0 >> 32) == tg) & ((unsigned)(b1 >> 32) == tg); }
    } while (!(oka && okb));
    *d1 = make_float2(__uint_as_float((unsigned)a0), __uint_as_float((unsigned)a1));
    *d2 = make_float2(__uint_as_float((unsigned)b0), __uint_as_float((unsigned)b1));
}

// reconstruct h[8k..8k+8) from split A/B arrays (conflict-free LDS.128)
__device__ __forceinline__ void ld8f2(const float* A, const float* B, int k, float* f) {
    float4 a = ((const float4*)A)[k];
    float4 b = ((const float4*)B)[k];
    f[0] = a.x; f[1] = a.y; f[2] = a.z; f[3] = a.w;
    f[4] = b.x; f[5] = b.y; f[6] = b.z; f[7] = b.w;
}

// load 8 consecutive fp32 from gmem into register array
__device__ __forceinline__ void ld8g(const float* p, float* f) {
    float4 a = __ldg((const float4*)p);
    float4 b = __ldg((const float4*)p + 1);
    f[0] = a.x; f[1] = a.y; f[2] = a.z; f[3] = a.w;
    f[4] = b.x; f[5] = b.y; f[6] = b.z; f[7] = b.w;
}

__global__ void __launch_bounds__(NTH, 1)
lstm_persistent(const float* __restrict__ x,
                const float* __restrict__ Wih1, const float* __restrict__ Whh1,
                const float* __restrict__ bih1, const float* __restrict__ bhh1,
                const float* __restrict__ Wih2, const float* __restrict__ Whh2,
                const float* __restrict__ bih2, const float* __restrict__ bhh2,
                const float* __restrict__ Wout, const float* __restrict__ bout,
                float* __restrict__ out)
{
    extern __shared__ unsigned char sm[];
    float*  sH1A  = (float*)sm;                  // h1(t) elements idx%8<4 (512 f)
    float*  sH1B  = sH1A + 512;                  // h1(t) elements idx%8>=4
    float*  sH2A  = sH1B + 512;                  // h2(t-1) split likewise
    float*  sH2B  = sH2A + 512;
    float*  sP    = sH2B + 512;                  // [8 hidden][8]: a1 g0..3, a2 g0..3

    const int tid  = threadIdx.x;
    const int w    = tid >> 5;
    const int lane = tid & 31;
    const int b    = blockIdx.x;
    const int j    = w >> 1;        // hidden unit this warp-pair owns
    const int odd  = w & 1;         // 0: gates 0,1 + h1 cell; 1: gates 2,3 + h2 cell
    const int jg   = 8 * b + j;

    // conflict-free staging slots for this thread's polled float2s
    const int mgrp = tid >> 2, msub = tid & 3;
    const int slot = 2 * mgrp + (msub & 1);
    float2* d1 = (float2*)((msub < 2) ? sH1A : sH1B) + slot;
    float2* d2 = (float2*)((msub < 2) ? sH2A : sH2B) + slot;

    // ---- weight rows r0=2w, r1=2w+1 of each big matrix -> fp32 REGISTERS ----
    // row r: gate g = r&3, hidden jj = r>>2 = j; source row = g*HID + jg
    float W11a[4][8], W11b[4][8], Wi2a[4][8], Wi2b[4][8], Wh2a[4][8], Wh2b[4][8];
    {
        const size_t rb0 = ((size_t)((2 * w) & 3) * HID + (size_t)jg) * HID;
        const size_t rb1 = ((size_t)((2 * w + 1) & 3) * HID + (size_t)jg) * HID;
#pragma unroll
        for (int c = 0; c < 4; ++c) {
            int k = lane + 32 * c;
            ld8g(Whh1 + rb0 + 8 * k, W11a[c]);
            ld8g(Whh1 + rb1 + 8 * k, W11b[c]);
            ld8g(Wih2 + rb0 + 8 * k, Wi2a[c]);
            ld8g(Wih2 + rb1 + 8 * k, Wi2b[c]);
            ld8g(Whh2 + rb0 + 8 * k, Wh2a[c]);
            ld8g(Whh2 + rb1 + 8 * k, Wh2b[c]);
        }
    }
    // ---- Wih1 rows r0,r1 -> registers (fp32, float2 per lane) ----
    float2 wx0, wx1;
    {
        const size_t xb0 = ((size_t)((2 * w) & 3) * HID + (size_t)jg) * 64;
        const size_t xb1 = ((size_t)((2 * w + 1) & 3) * HID + (size_t)jg) * 64;
        wx0 = __ldg((const float2*)(Wih1 + xb0) + lane);
        wx1 = __ldg((const float2*)(Wih1 + xb1) + lane);
    }

    // ---- clear stale tags (both parities), then seed h2(-1)=0 with tag 1 ----
    if (tid < 8) {
        int j8 = 8 * b + tid;
        __stcg(&g_h1q[0][j8], 0ull);
        __stcg(&g_h1q[1][j8], 0ull);
        __stcg(&g_h2q[0][j8], 0ull);
        __stcg(&g_h2q[1][j8], (1ull << 32));   // tag 1, value fp32(0)
    }

    // ---- cell role: lane0 of even warp -> L1 cell of hidden j; odd -> L2 cell ----
    float bsum[4] = {0.f, 0.f, 0.f, 0.f};
    if (lane == 0) {
        const float* bi = odd ? bih2 : bih1;
        const float* bh = odd ? bhh2 : bhh1;
#pragma unroll
        for (int g = 0; g < 4; ++g)
            bsum[g] = __ldg(bi + g * HID + jg) + __ldg(bh + g * HID + jg);
    }
    float cstate = 0.0f;

    // ---- output-projection role (warp 15 of CTA 1 -> col0, CTA 65 -> col1) ----
    const bool outcta = (b == 1 || b == 65);
    const bool outw = (w == 15) && outcta;
    const int  oi   = (b == 65) ? 1 : 0;
    float bo = 0.0f;
    if (outw && lane == 0) bo = __ldg(bout + oi);
    const float4* worow = (const float4*)(Wout + oi * HID);

    gridbar();   // stale tags cleared everywhere before anyone publishes/polls

    // ---- prologue: h1(0) = gates(Wih1 @ x(0) + biases); publish tag 1 ----
    {
        float2 xv = __ldg((const float2*)x + lane);
        float a0 = warpsum(fmaf(wx0.x, xv.x, wx0.y * xv.y));
        float a1 = warpsum(fmaf(wx1.x, xv.x, wx1.y * xv.y));
        if (lane == 0) { sP[j * 8 + odd * 2] = a0; sP[j * 8 + odd * 2 + 1] = a1; }
        __syncthreads();
        if (lane == 0 && odd == 0) {
            float gi = sP[j * 8 + 0] + bsum[0];
            float gg = sP[j * 8 + 2] + bsum[2];
            float go = sP[j * 8 + 3] + bsum[3];
            cstate = sigf(gi) * tanhfast(gg);
            float h = sigf(go) * tanhfast(cstate);
            unsigned long long word = (1ull << 32)
                                    | (unsigned long long)__float_as_uint(h);
            __stcg(&g_h1q[0][jg], word);
        }
        __syncthreads();   // cell reads of sP done before t=0 writes it
    }

    // poll pointers per parity (this thread's 2 words of each array)
    const unsigned long long* h1p[2] = { &g_h1q[0][2 * tid], &g_h1q[1][2 * tid] };
    const unsigned long long* h2p[2] = { &g_h2q[0][2 * tid], &g_h2q[1][2 * tid] };

    // ==== main loop: interval t consumes h1(t),h2(t-1); publishes h2(t),h1(t+1) ====
    for (int t = 0; t < TSTEPS; ++t) {
        const int p1 = t & 1;
        const int p2 = p1 ^ 1;
        const unsigned tg = (unsigned)(t + 1);

        // ---- fused data-carrying barrier: poll BOTH arrays, stage in one pass ----
        poll_stage(h1p[p1], h2p[p2], tg, d1, d2);
        __syncthreads();

        // ---- dots from REGISTER weights (same FMA order as r15) ----
        float a1x = 0.f, a1y = 0.f, a2x = 0.f, a2y = 0.f;
#pragma unroll
        for (int c = 0; c < 4; ++c) {
            int k = lane + 32 * c;
            float h1f[8], h2f[8];
            ld8f2(sH1A, sH1B, k, h1f);
            ld8f2(sH2A, sH2B, k, h2f);
#pragma unroll
            for (int e = 0; e < 8; ++e) a1x = fmaf(W11a[c][e], h1f[e], a1x);
#pragma unroll
            for (int e = 0; e < 8; ++e) a1y = fmaf(W11b[c][e], h1f[e], a1y);
#pragma unroll
            for (int e = 0; e < 8; ++e) a2x = fmaf(Wi2a[c][e], h1f[e], a2x);
#pragma unroll
            for (int e = 0; e < 8; ++e) a2y = fmaf(Wi2b[c][e], h1f[e], a2y);
#pragma unroll
            for (int e = 0; e < 8; ++e) a2x = fmaf(Wh2a[c][e], h2f[e], a2x);
#pragma unroll
            for (int e = 0; e < 8; ++e) a2y = fmaf(Wh2b[c][e], h2f[e], a2y);
        }
        // + Wih1 @ x(t+1) into layer-1 rows
        {
            float2 xv = make_float2(0.f, 0.f);
            if (t + 1 < TSTEPS)
                xv = __ldg((const float2*)(x + (size_t)(t + 1) * 64) + lane);
            a1x = fmaf(wx0.x, xv.x, fmaf(wx0.y, xv.y, a1x));
            a1y = fmaf(wx1.x, xv.x, fmaf(wx1.y, xv.y, a1y));
        }

        a1x = warpsum(a1x); a1y = warpsum(a1y);
        a2x = warpsum(a2x); a2y = warpsum(a2y);
        if (lane == 0) {
            sP[j * 8 + odd * 2]     = a1x;
            sP[j * 8 + odd * 2 + 1] = a1y;
            sP[j * 8 + 4 + odd * 2]     = a2x;
            sP[j * 8 + 4 + odd * 2 + 1] = a2y;
        }
        // group barrier: 4 warps (2 warp-pairs) converge, then cells publish early
        asm volatile("bar.sync %0, 128;" :: "r"(1 + (w >> 2)) : "memory");

        // ---- cells: even lane0 -> h1(t+1); odd lane0 -> h2(t); publish tagged ----
        if (lane == 0) {
            const float* g4 = sP + j * 8 + odd * 4;   // a1 block or a2 block
            float gi = g4[0] + bsum[0];
            float gf = g4[1] + bsum[1];
            float gg = g4[2] + bsum[2];
            float go = g4[3] + bsum[3];
            cstate = sigf(gf) * cstate + sigf(gi) * tanhfast(gg);
            float h = sigf(go) * tanhfast(cstate);
            unsigned long long word = ((unsigned long long)(t + 2) << 32)
                                    | (unsigned long long)__float_as_uint(h);
            if (odd == 0) __stcg(&g_h1q[p2][jg], word);   // h1(t+1)
            else          __stcg(&g_h2q[p1][jg], word);   // h2(t)
        }

        // ---- out duty (off the publish path): out[t-1] = Wout @ h2(t-1) ----
        if (outw && t > 0) {
            float a = 0.f;
#pragma unroll
            for (int c = 0; c < 4; ++c) {
                int k = lane + 32 * c;
                float hf[8]; ld8f2(sH2A, sH2B, k, hf);
                float4 wa = __ldg(worow + 2 * k);
                float4 wb = __ldg(worow + 2 * k + 1);
                a = fmaf(wa.x, hf[0], fmaf(wa.y, hf[1], fmaf(wa.z, hf[2], fmaf(wa.w, hf[3], a))));
                a = fmaf(wb.x, hf[4], fmaf(wb.y, hf[5], fmaf(wb.z, hf[6], fmaf(wb.w, hf[7], a))));
            }
            a = warpsum(a);
            if (lane == 0) out[(t - 1) * 2 + oi] = a + bo;
        }

        // trailing CTA sync: orders sH/sP reads before next interval's writes
        __syncthreads();
    }

    // ---- epilogue: out[T-1] from h2(T-1) (tag 4097, parity 1) ----
    if (outcta) {
        {
            unsigned long long b0v, b1v;
            const unsigned tgf = (unsigned)(TSTEPS + 1);
            bool ok = false;
            do { ldcg2q(h2p[1], b0v, b1v);
                 ok = ((unsigned)(b0v >> 32) == tgf) & ((unsigned)(b1v >> 32) == tgf);
            } while (!ok);
            *d2 = make_float2(__uint_as_float((unsigned)b0v),
                              __uint_as_float((unsigned)b1v));
        }
        __syncthreads();
        if (outw) {
            float a = 0.f;
#pragma unroll
            for (int c = 0; c < 4; ++c) {
                int k = lane + 32 * c;
                float hf[8]; ld8f2(sH2A, sH2B, k, hf);
                float4 wa = __ldg(worow + 2 * k);
                float4 wb = __ldg(worow + 2 * k + 1);
                a = fmaf(wa.x, hf[0], fmaf(wa.y, hf[1], fmaf(wa.z, hf[2], fmaf(wa.w, hf[3], a))));
                a = fmaf(wb.x, hf[4], fmaf(wb.y, hf[5], fmaf(wb.z, hf[6], fmaf(wb.w, hf[7], a))));
            }
            a = warpsum(a);
            if (lane == 0) out[(TSTEPS - 1) * 2 + oi] = a + bo;
        }
    }
}

extern "C" void kernel_launch(void* const* d_in, const int* in_sizes, int n_in,
                              void* d_out, int out_size)
{
    const float* x    = (const float*)d_in[0];
    const float* Wih1 = (const float*)d_in[1];
    const float* Whh1 = (const float*)d_in[2];
    const float* bih1 = (const float*)d_in[3];
    const float* bhh1 = (const float*)d_in[4];
    const float* Wih2 = (const float*)d_in[5];
    const float* Whh2 = (const float*)d_in[6];
    const float* bih2 = (const float*)d_in[7];
    const float* bhh2 = (const float*)d_in[8];
    const float* Wout = (const float*)d_in[9];
    const float* bout = (const float*)d_in[10];
    float* out = (float*)d_out;

    cudaFuncSetAttribute(lstm_persistent,
                         cudaFuncAttributeMaxDynamicSharedMemorySize, SMEM_BYTES);

    lstm_persistent<<<NCTA, NTH, SMEM_BYTES>>>(x, Wih1, Whh1, bih1, bhh1,
                                               Wih2, Whh2, bih2, bhh2,
                                               Wout, bout, out);
}